// round 6
// baseline (speedup 1.0000x reference)
#include <cuda_runtime.h>
#include <math.h>

#define NCLS 1000
#define NV4  250   // 1000 floats = 250 float4 per row

// Monotone float -> u32 map (order-preserving; 0 is the bottom identity)
__device__ __forceinline__ unsigned fmap(float x) {
    int i = __float_as_int(x);
    return (i < 0) ? ~(unsigned)i : ((unsigned)i | 0x80000000u);
}
__device__ __forceinline__ float funmap(unsigned u) {
    int i = (u & 0x80000000u) ? (int)(u & 0x7FFFFFFFu) : ~(int)u;
    return __int_as_float(i);
}

// Self-resetting cross-launch scratch (zero at load; last block re-zeros)
__device__ unsigned g_gmax  = 0;
__device__ unsigned g_count = 0;

__global__ __launch_bounds__(256, 8) void margin_kernel(
    const float* __restrict__ o1, const float* __restrict__ o2,
    const float* __restrict__ o3, const float* __restrict__ o4,
    const float* __restrict__ mim, const int* __restrict__ targets,
    float* __restrict__ out_max, float* __restrict__ out_thr)
{
    const int tid  = threadIdx.x;
    const int row0 = blockIdx.x * 2;

    const float* mats[5] = {o1, o2, o3, o4, mim};

    __shared__ float    s_tgt[2][5];
    __shared__ unsigned s_red[2][5][8];

    int t[2];
    t[0] = targets[row0];
    t[1] = targets[row0 + 1];

    // ---- load phase: 10 independent streaming float4 loads per thread ----
    float4 v[2][5];
    const bool active = (tid < NV4);
    if (active) {
        #pragma unroll
        for (int r = 0; r < 2; r++) {
            const size_t base = (size_t)(row0 + r) * NCLS;
            #pragma unroll
            for (int m = 0; m < 5; m++)
                v[r][m] = __ldcs(reinterpret_cast<const float4*>(mats[m] + base) + tid);
        }
    }

    // ---- per-thread max (excluding target) + target capture, per row ----
    unsigned u[2][5];
    #pragma unroll
    for (int r = 0; r < 2; r++) {
        const int town = t[r] >> 2, tsub = t[r] & 3;
        const bool own = (tid == town);
        #pragma unroll
        for (int m = 0; m < 5; m++) {
            float a = -INFINITY, b = -INFINITY, c = -INFINITY, d = -INFINITY;
            if (active) { a = v[r][m].x; b = v[r][m].y; c = v[r][m].z; d = v[r][m].w; }
            float mx = fmaxf(fmaxf(a, b), fmaxf(c, d));
            if (own) {
                float tv = (tsub == 0) ? a : (tsub == 1) ? b : (tsub == 2) ? c : d;
                s_tgt[r][m] = tv;
                float ea = (tsub == 0) ? -INFINITY : a;
                float eb = (tsub == 1) ? -INFINITY : b;
                float ec = (tsub == 2) ? -INFINITY : c;
                float ed = (tsub == 3) ? -INFINITY : d;
                mx = fmaxf(fmaxf(ea, eb), fmaxf(ec, ed));
            }
            u[r][m] = fmap(mx);
        }
    }

    // ---- warp reduction: one REDUX per (row, matrix) ----
    #pragma unroll
    for (int r = 0; r < 2; r++)
        #pragma unroll
        for (int m = 0; m < 5; m++)
            u[r][m] = __reduce_max_sync(0xFFFFFFFFu, u[r][m]);

    const int warp = tid >> 5, lane = tid & 31;
    if (lane == 0) {
        #pragma unroll
        for (int r = 0; r < 2; r++)
            #pragma unroll
            for (int m = 0; m < 5; m++) s_red[r][m][warp] = u[r][m];
    }
    __syncthreads();

    // ---- epilogue: lane 0 -> row 0, lane 1 -> row 1 (same warp) ----
    if (tid < 2) {
        const int r = tid;
        float m_excl[5];
        #pragma unroll
        for (int m = 0; m < 5; m++) {
            unsigned um = s_red[r][m][0];
            #pragma unroll
            for (int w = 1; w < 8; w++) um = max(um, s_red[r][m][w]);
            m_excl[m] = funmap(um);
        }

        // row max over mats 0..3 (restore excluded target element)
        float g = -INFINITY;
        #pragma unroll
        for (int m = 0; m < 4; m++) g = fmaxf(g, fmaxf(m_excl[m], s_tgt[r][m]));

        // margin = max(0, tgt - max_excl), /TEMPERATURE(=2) folded in
        float margin[5];
        #pragma unroll
        for (int m = 0; m < 5; m++)
            margin[m] = fmaxf(0.0f, (s_tgt[r][m] - m_excl[m]) * 0.5f);

        float mx = margin[0];
        #pragma unroll
        for (int m = 1; m < 5; m++) mx = fmaxf(mx, margin[m]);
        float e[5], s = 0.0f;
        #pragma unroll
        for (int m = 0; m < 5; m++) { e[m] = __expf(margin[m] - mx); s += e[m]; }
        float inv = 1.0f / s;
        float* dst = out_thr + (size_t)(row0 + r) * 5;
        #pragma unroll
        for (int m = 0; m < 5; m++) dst[m] = e[m] * inv;

        // combine the two rows' maxima within the warp, lane 0 does the atomic
        float gpeer = __shfl_sync(0x3u, g, 1, 32);
        if (tid == 0) {
            float gblk = fmaxf(g, gpeer);
            atomicMax(&g_gmax, fmap(gblk));
            __threadfence();
            unsigned c = atomicAdd(&g_count, 1);
            if (c == gridDim.x - 1) {      // last block publishes + resets
                unsigned final_u = atomicMax(&g_gmax, 0u);
                *out_max = funmap(final_u);
                atomicExch(&g_gmax, 0u);
                atomicExch(&g_count, 0u);
            }
        }
    }
}

extern "C" void kernel_launch(void* const* d_in, const int* in_sizes, int n_in,
                              void* d_out, int out_size)
{
    const float* o1  = (const float*)d_in[0];
    const float* o2  = (const float*)d_in[1];
    const float* o3  = (const float*)d_in[2];
    const float* o4  = (const float*)d_in[3];
    const float* mim = (const float*)d_in[4];
    const int*   tgt = (const int*)d_in[5];

    const int n = in_sizes[5];          // 16384 rows (even)
    float* out = (float*)d_out;

    float* out_thr = out + ((size_t)out_size - (size_t)n * 5);
    float* out_max = out;

    margin_kernel<<<n / 2, 256>>>(o1, o2, o3, o4, mim, tgt, out_max, out_thr);
}

// round 7
// speedup vs baseline: 1.7552x; 1.7552x over previous
#include <cuda_runtime.h>
#include <math.h>

#define NCLS 1000
#define NV4  250   // 1000 floats = 250 float4 per row

// Monotone float -> u32 map (order-preserving; 0 is the bottom identity)
__device__ __forceinline__ unsigned fmap(float x) {
    int i = __float_as_int(x);
    return (i < 0) ? ~(unsigned)i : ((unsigned)i | 0x80000000u);
}
__device__ __forceinline__ float funmap(unsigned u) {
    int i = (u & 0x80000000u) ? (int)(u & 0x7FFFFFFFu) : ~(int)u;
    return __int_as_float(i);
}

// Self-resetting cross-launch scratch (zero at load; last block re-zeros)
__device__ unsigned g_gmax  = 0;
__device__ unsigned g_count = 0;

__global__ __launch_bounds__(256, 8) void margin_kernel(
    const float* __restrict__ o1, const float* __restrict__ o2,
    const float* __restrict__ o3, const float* __restrict__ o4,
    const float* __restrict__ mim, const int* __restrict__ targets,
    float* __restrict__ out_max, float* __restrict__ out_thr, int n)
{
    const int tid  = threadIdx.x;
    const int warp = tid >> 5, lane = tid & 31;
    const bool active = (tid < NV4);

    const float* mats[5] = {o1, o2, o3, o4, mim};

    // parity double-buffered so one __syncthreads per row suffices:
    // warps write buffer p for row i while thread 0 still reads buffer p^1 of row i-1
    __shared__ float    s_tgt[2][5];
    __shared__ unsigned s_red[2][5][8];

    float gblk = -INFINITY;
    int par = 0;

    for (int row = blockIdx.x; row < n; row += gridDim.x, par ^= 1) {
        const int t = targets[row];
        const int town = t >> 2, tsub = t & 3;
        const bool own = (tid == town);

        // ---- 5 independent streaming float4 loads (20 data regs) ----
        float4 v[5];
        if (active) {
            const size_t base = (size_t)row * NCLS;
            #pragma unroll
            for (int m = 0; m < 5; m++)
                v[m] = __ldcs(reinterpret_cast<const float4*>(mats[m] + base) + tid);
        }

        // ---- per-thread max (excluding target element) + target capture ----
        unsigned u[5];
        #pragma unroll
        for (int m = 0; m < 5; m++) {
            float a = -INFINITY, b = -INFINITY, c = -INFINITY, d = -INFINITY;
            if (active) { a = v[m].x; b = v[m].y; c = v[m].z; d = v[m].w; }
            float mx = fmaxf(fmaxf(a, b), fmaxf(c, d));
            if (own) {
                float tv = (tsub == 0) ? a : (tsub == 1) ? b : (tsub == 2) ? c : d;
                s_tgt[par][m] = tv;
                float ea = (tsub == 0) ? -INFINITY : a;
                float eb = (tsub == 1) ? -INFINITY : b;
                float ec = (tsub == 2) ? -INFINITY : c;
                float ed = (tsub == 3) ? -INFINITY : d;
                mx = fmaxf(fmaxf(ea, eb), fmaxf(ec, ed));
            }
            u[m] = fmap(mx);
        }

        // ---- warp reduction: single REDUX per matrix ----
        #pragma unroll
        for (int m = 0; m < 5; m++)
            u[m] = __reduce_max_sync(0xFFFFFFFFu, u[m]);

        if (lane == 0) {
            #pragma unroll
            for (int m = 0; m < 5; m++) s_red[par][m][warp] = u[m];
        }
        __syncthreads();   // orders this row's smem writes; also protects buffer reuse

        // ---- epilogue (thread 0); other warps proceed to next row's loads ----
        if (tid == 0) {
            float m_excl[5];
            #pragma unroll
            for (int m = 0; m < 5; m++) {
                unsigned um = s_red[par][m][0];
                #pragma unroll
                for (int w = 1; w < 8; w++) um = max(um, s_red[par][m][w]);
                m_excl[m] = funmap(um);
            }

            // row max over mats 0..3 (restore excluded target element)
            float g = -INFINITY;
            #pragma unroll
            for (int m = 0; m < 4; m++) g = fmaxf(g, fmaxf(m_excl[m], s_tgt[par][m]));
            gblk = fmaxf(gblk, g);

            // margin = max(0, tgt - max_excl), /TEMPERATURE(=2) folded in
            float margin[5];
            #pragma unroll
            for (int m = 0; m < 5; m++)
                margin[m] = fmaxf(0.0f, (s_tgt[par][m] - m_excl[m]) * 0.5f);

            float mx = margin[0];
            #pragma unroll
            for (int m = 1; m < 5; m++) mx = fmaxf(mx, margin[m]);
            float e[5], s = 0.0f;
            #pragma unroll
            for (int m = 0; m < 5; m++) { e[m] = __expf(margin[m] - mx); s += e[m]; }
            float inv = 1.0f / s;
            float* dst = out_thr + (size_t)row * 5;
            #pragma unroll
            for (int m = 0; m < 5; m++) dst[m] = e[m] * inv;
        }
    }

    // ---- one atomic per block; last block publishes + resets scratch ----
    if (tid == 0) {
        atomicMax(&g_gmax, fmap(gblk));
        __threadfence();
        unsigned c = atomicAdd(&g_count, 1);
        if (c == gridDim.x - 1) {
            unsigned final_u = atomicMax(&g_gmax, 0u);
            *out_max = funmap(final_u);
            atomicExch(&g_gmax, 0u);
            atomicExch(&g_count, 0u);
        }
    }
}

extern "C" void kernel_launch(void* const* d_in, const int* in_sizes, int n_in,
                              void* d_out, int out_size)
{
    const float* o1  = (const float*)d_in[0];
    const float* o2  = (const float*)d_in[1];
    const float* o3  = (const float*)d_in[2];
    const float* o4  = (const float*)d_in[3];
    const float* mim = (const float*)d_in[4];
    const int*   tgt = (const int*)d_in[5];

    const int n = in_sizes[5];          // 16384 rows
    float* out = (float*)d_out;

    float* out_thr = out + ((size_t)out_size - (size_t)n * 5);
    float* out_max = out;

    int grid = 148 * 8;                 // persistent: one wave, 8 CTAs/SM
    if (grid > n) grid = n;

    margin_kernel<<<grid, 256>>>(o1, o2, o3, o4, mim, tgt, out_max, out_thr, n);
}

// round 8
// speedup vs baseline: 1.7678x; 1.0072x over previous
#include <cuda_runtime.h>
#include <math.h>

#define NCLS 1000
#define NV4  250   // 1000 floats = 250 float4 per row

// Monotone float -> u32 map (order-preserving; 0 is the bottom identity)
__device__ __forceinline__ unsigned fmap(float x) {
    int i = __float_as_int(x);
    return (i < 0) ? ~(unsigned)i : ((unsigned)i | 0x80000000u);
}
__device__ __forceinline__ float funmap(unsigned u) {
    int i = (u & 0x80000000u) ? (int)(u & 0x7FFFFFFFu) : ~(int)u;
    return __int_as_float(i);
}

// Self-resetting cross-launch scratch (zero at load; last block re-zeros)
__device__ unsigned g_gmax  = 0;
__device__ unsigned g_count = 0;

__global__ __launch_bounds__(256, 6) void margin_kernel(
    const float* __restrict__ o1, const float* __restrict__ o2,
    const float* __restrict__ o3, const float* __restrict__ o4,
    const float* __restrict__ mim, const int* __restrict__ targets,
    float* __restrict__ out_max, float* __restrict__ out_thr, int n)
{
    const int tid  = threadIdx.x;
    const int warp = tid >> 5, lane = tid & 31;
    const bool active = (tid < NV4);

    const float* mats[5] = {o1, o2, o3, o4, mim};

    // double-buffered (warps run at most 1 iteration ahead of thread 0)
    __shared__ float    s_tgt[2][5];
    __shared__ unsigned s_red[2][5][8];

    float gblk = -INFINITY;
    int par = 0;

    int row = blockIdx.x;
    int t_cur = (row < n) ? targets[row] : 0;

    // ---- prologue: load first row ----
    float4 v[5];
    if (active && row < n) {
        const size_t base = (size_t)row * NCLS;
        #pragma unroll
        for (int m = 0; m < 5; m++)
            v[m] = __ldcs(reinterpret_cast<const float4*>(mats[m] + base) + tid);
    }

    while (row < n) {
        const int row_next = row + gridDim.x;
        const int town = t_cur >> 2, tsub = t_cur & 3;
        const bool own = (tid == town);

        // ---- 1) consume v: per-thread max (excl. target) + target capture ----
        unsigned u[5];
        #pragma unroll
        for (int m = 0; m < 5; m++) {
            float a = -INFINITY, b = -INFINITY, c = -INFINITY, d = -INFINITY;
            if (active) { a = v[m].x; b = v[m].y; c = v[m].z; d = v[m].w; }
            float mx = fmaxf(fmaxf(a, b), fmaxf(c, d));
            if (own) {
                float tv = (tsub == 0) ? a : (tsub == 1) ? b : (tsub == 2) ? c : d;
                s_tgt[par][m] = tv;
                float ea = (tsub == 0) ? -INFINITY : a;
                float eb = (tsub == 1) ? -INFINITY : b;
                float ec = (tsub == 2) ? -INFINITY : c;
                float ed = (tsub == 3) ? -INFINITY : d;
                mx = fmaxf(fmaxf(ea, eb), fmaxf(ec, ed));
            }
            u[m] = fmap(mx);
        }

        // ---- 2) prefetch next row NOW (in flight across reduce+barrier+epi) ----
        int t_next = 0;
        if (row_next < n) {
            t_next = targets[row_next];
            if (active) {
                const size_t base = (size_t)row_next * NCLS;
                #pragma unroll
                for (int m = 0; m < 5; m++)
                    v[m] = __ldcs(reinterpret_cast<const float4*>(mats[m] + base) + tid);
            }
        }

        // ---- 3) warp reduction + block combine ----
        #pragma unroll
        for (int m = 0; m < 5; m++)
            u[m] = __reduce_max_sync(0xFFFFFFFFu, u[m]);

        if (lane == 0) {
            #pragma unroll
            for (int m = 0; m < 5; m++) s_red[par][m][warp] = u[m];
        }
        __syncthreads();

        // ---- 4) epilogue (thread 0); other warps roll into next iteration ----
        if (tid == 0) {
            float m_excl[5];
            #pragma unroll
            for (int m = 0; m < 5; m++) {
                unsigned um = s_red[par][m][0];
                #pragma unroll
                for (int w = 1; w < 8; w++) um = max(um, s_red[par][m][w]);
                m_excl[m] = funmap(um);
            }

            float g = -INFINITY;
            #pragma unroll
            for (int m = 0; m < 4; m++) g = fmaxf(g, fmaxf(m_excl[m], s_tgt[par][m]));
            gblk = fmaxf(gblk, g);

            float margin[5];
            #pragma unroll
            for (int m = 0; m < 5; m++)
                margin[m] = fmaxf(0.0f, (s_tgt[par][m] - m_excl[m]) * 0.5f);

            float mx = margin[0];
            #pragma unroll
            for (int m = 1; m < 5; m++) mx = fmaxf(mx, margin[m]);
            float e[5], s = 0.0f;
            #pragma unroll
            for (int m = 0; m < 5; m++) { e[m] = __expf(margin[m] - mx); s += e[m]; }
            float inv = 1.0f / s;
            float* dst = out_thr + (size_t)row * 5;
            #pragma unroll
            for (int m = 0; m < 5; m++) dst[m] = e[m] * inv;
        }

        t_cur = t_next;
        row = row_next;
        par ^= 1;
    }

    // ---- one atomic per block; last block publishes + resets scratch ----
    if (tid == 0) {
        atomicMax(&g_gmax, fmap(gblk));
        __threadfence();
        unsigned c = atomicAdd(&g_count, 1);
        if (c == gridDim.x - 1) {
            unsigned final_u = atomicMax(&g_gmax, 0u);
            *out_max = funmap(final_u);
            atomicExch(&g_gmax, 0u);
            atomicExch(&g_count, 0u);
        }
    }
}

extern "C" void kernel_launch(void* const* d_in, const int* in_sizes, int n_in,
                              void* d_out, int out_size)
{
    const float* o1  = (const float*)d_in[0];
    const float* o2  = (const float*)d_in[1];
    const float* o3  = (const float*)d_in[2];
    const float* o4  = (const float*)d_in[3];
    const float* mim = (const float*)d_in[4];
    const int*   tgt = (const int*)d_in[5];

    const int n = in_sizes[5];          // 16384 rows
    float* out = (float*)d_out;

    float* out_thr = out + ((size_t)out_size - (size_t)n * 5);
    float* out_max = out;

    int grid = 148 * 6;                 // persistent, 6 CTAs/SM (42-reg budget)
    if (grid > n) grid = n;

    margin_kernel<<<grid, 256>>>(o1, o2, o3, o4, mim, tgt, out_max, out_thr, n);
}